// round 14
// baseline (speedup 1.0000x reference)
#include <cuda_runtime.h>

#define NN 32768
#define GG 256
#define PP 128
#define EE 524288
#define HH 64
#define CAP 96
#define ROWS (GG*(PP-1))

typedef unsigned long long ull;

// ---- device scratch ----
__device__ __align__(16) float g_h[(NN+1)*HH];   // +1 sentinel zero row
__device__ __align__(16) float g_m[(NN+1)*HH];
__device__ __align__(16) float g_s[NN*HH];       // gathered messages scratch
__device__ __align__(16) float g_Ag[GG*HH*HH];
__device__ __align__(16) float g_AB[HH*HH*2];    // A table [0,4096), B table [4096,8192), k-pair packed
__device__ __align__(16) float g_c[HH];
__device__ __align__(16) int g_deg[NN];          // zeroed at end of k_ag each replay
__device__ int g_srcl[NN*CAP];

// ---- f32x2 helpers ----
__device__ __forceinline__ ull pk2(float x, float y) {
    ull r; asm("mov.b64 %0,{%1,%2};" : "=l"(r) : "f"(x), "f"(y)); return r;
}
__device__ __forceinline__ ull ff2(ull a, ull b, ull c) {
    ull d; asm("fma.rn.f32x2 %0,%1,%2,%3;" : "=l"(d) : "l"(a), "l"(b), "l"(c)); return d;
}
__device__ __forceinline__ ull ad2(ull a, ull b) {
    ull d; asm("add.rn.f32x2 %0,%1,%2;" : "=l"(d) : "l"(a), "l"(b)); return d;
}
__device__ __forceinline__ float2 up2(ull a) {
    float x, y; asm("mov.b64 {%0,%1},%2;" : "=f"(x), "=f"(y) : "l"(a));
    return make_float2(x, y);
}

// ---- launch 1: weights (blk 0-15), bias+sentinel (blk 16), input layer (17-528),
//                CSR bucket fill (blk 529-1552, overlapped) ----
__global__ void k_pi(const float* __restrict__ x, const void* __restrict__ ei,
                     const float* __restrict__ W1, const float* __restrict__ b1,
                     const float* __restrict__ W2, const float* __restrict__ b2,
                     const float* __restrict__ W3, const float* __restrict__ b3,
                     const float* __restrict__ W4, const float* __restrict__ b4) {
    int tid = threadIdx.x;
    if (blockIdx.x >= 529) {
        // ---- CSR fill, 2 edges/thread; local int64 detection (256 high-words) ----
        const int* ei32 = (const int*)ei;
        int bad = (ei32[2*tid + 1] != 0);
        int is64 = !__syncthreads_or(bad);
        int e = ((int)(blockIdx.x - 529)*256 + tid)*2;
        int s0, s1, d0, d1;
        if (is64) {
            longlong2 sv = *(const longlong2*)((const long long*)ei + e);
            longlong2 dv = *(const longlong2*)((const long long*)ei + EE + e);
            s0 = (int)sv.x; s1 = (int)sv.y; d0 = (int)dv.x; d1 = (int)dv.y;
        } else {
            int2 sv = *(const int2*)(ei32 + e);
            int2 dv = *(const int2*)(ei32 + EE + e);
            s0 = sv.x; s1 = sv.y; d0 = dv.x; d1 = dv.y;
        }
        int p0 = atomicAdd(&g_deg[d0], 1);
        g_srcl[d0*CAP + p0] = s0;
        int p1 = atomicAdd(&g_deg[d1], 1);
        g_srcl[d1*CAP + p1] = s1;
        return;
    }
    if (blockIdx.x < 16) {
        int e = blockIdx.x * 256 + tid;
        int o = e >> 6, k = e & 63;
        float a = 0.f, b = 0.f;
        for (int t = 0; t < 64; ++t) {
            a += W4[o*128 + t]      * W3[t*64 + k];
            b += W4[o*128 + 64 + t] * W2[t*64 + k];
        }
        // k-pair packed: float4 at (kp*32 + (o&31)) = {X[o][2kp],X[o][2kp+1],X[o+32][2kp],X[o+32][2kp+1]}
        int kp = k >> 1, ob = o & 31, comp = ((o >> 5) << 1) | (k & 1);
        g_AB[(kp*32 + ob)*4 + comp]        = a;
        g_AB[4096 + (kp*32 + ob)*4 + comp] = b;
        return;
    }
    if (blockIdx.x == 16) {
        if (tid < 64) {
            float c = b4[tid];
            for (int t = 0; t < 64; ++t)
                c += W4[tid*128 + t]*b3[t] + W4[tid*128 + 64 + t]*b2[t];
            g_c[tid] = c;
            g_h[NN*64 + tid] = 0.f;   // sentinel rows
            g_m[NN*64 + tid] = 0.f;
        }
        return;
    }
    // ---- input layer ----
    __shared__ __align__(16) float sW[8*64];
    __shared__ float sb[64];
    for (int e = tid; e < 512; e += 256) {
        int o = e >> 3, j = e & 7;
        sW[j*64 + o] = W1[e];
    }
    if (tid < 64) sb[tid] = b1[tid];
    __syncthreads();
    int lane = tid & 31, warp = tid >> 5;
    for (int node = (blockIdx.x - 17)*8 + warp; node < NN; node += 512*8) {
        float xv = (lane < 8) ? x[node*8 + lane] : 0.f;
        float a0 = sb[2*lane], a1 = sb[2*lane + 1];
        #pragma unroll
        for (int j = 0; j < 8; ++j) {
            float xj = __shfl_sync(0xffffffffu, xv, j);
            a0 += sW[j*64 + 2*lane]     * xj;
            a1 += sW[j*64 + 2*lane + 1] * xj;
        }
        a0 = fmaxf(a0, 0.f); a1 = fmaxf(a1, 0.f);
        float s = a0*a0 + a1*a1;
        #pragma unroll
        for (int off = 16; off; off >>= 1) s += __shfl_xor_sync(0xffffffffu, s, off);
        float rn = rsqrtf(s);
        ((float2*)g_h)[node*32 + lane] = make_float2(a0*rn, a1*rn);
    }
}

// ---- pure gather v2: half-warp float4 edges (2 edges/step, LDG.128) ----
__global__ void __launch_bounds__(512)
k_gat(const float* __restrict__ hin, float* __restrict__ mout) {
    int tid = threadIdx.x;
    int lane = tid & 31, warp = tid >> 5;
    int half = lane >> 4, hl = lane & 15;
    int nb = (blockIdx.x*16 + warp)*4;
    const float4* hin4 = (const float4*)hin;
    int deg[4], idx[4];
    #pragma unroll
    for (int t = 0; t < 4; ++t) deg[t] = g_deg[nb + t];
    #pragma unroll
    for (int t = 0; t < 4; ++t) {
        int n = deg[t] < 32 ? deg[t] : 32;
        idx[t] = (lane < n) ? g_srcl[(nb + t)*CAP + lane] : NN;
    }
    #pragma unroll
    for (int t = 0; t < 4; ++t) {
        int n = deg[t] < 32 ? deg[t] : 32;
        ull a0 = 0ULL, a1 = 0ULL;               // this half-warp's float4 partial
        int nr = (n + 1) & ~1;
        #pragma unroll 8
        for (int j = 0; j < nr; j += 2) {
            int s = __shfl_sync(0xffffffffu, idx[t], j + half);  // edge j (lo half) / j+1 (hi half)
            float4 row = hin4[s*16 + hl];
            a0 = ad2(a0, pk2(row.x, row.y));
            a1 = ad2(a1, pk2(row.z, row.w));
        }
        // rare tail (deg > 32)
        for (int b = 32; b < deg[t]; b += 2) {
            int rem = deg[t] - b;
            int s;
            if (half == 0 || rem > 1) s = g_srcl[(nb + t)*CAP + b + half];
            else s = NN;
            float4 row = hin4[s*16 + hl];
            a0 = ad2(a0, pk2(row.x, row.y));
            a1 = ad2(a1, pk2(row.z, row.w));
        }
        // fold the two half-warps: lane l (<16) += lane l+16 (same float range)
        a0 = ad2(a0, __shfl_xor_sync(0xffffffffu, a0, 16));
        a1 = ad2(a1, __shfl_xor_sync(0xffffffffu, a1, 16));
        if (half == 0) {
            float2 lo = up2(a0), hi = up2(a1);
            ((float4*)mout)[(nb + t)*16 + hl] = make_float4(lo.x, lo.y, hi.x, hi.y);
        }
    }
}

// ---- dense update: hout = normalize(relu(A@m + B@h + c)); 8 nodes/warp, weight-amortized ----
__global__ void __launch_bounds__(256, 3)
k_up(const float* __restrict__ hin, const float* __restrict__ min,
     float* __restrict__ hout) {
    extern __shared__ __align__(16) float4 dynsm[];
    float4* sWA = dynsm;          // 1024 float4 = 16KB
    float4* sWB = dynsm + 1024;   // 1024 float4 = 16KB
    ulonglong2* sX = (ulonglong2*)(dynsm + 2048);  // 8 warps * 8 nodes * 32 kp = 32KB
    int tid = threadIdx.x;
    for (int e = tid; e < 2048; e += 256) sWA[e] = ((const float4*)g_AB)[e];
    __syncthreads();
    int lane = tid & 31, warp = tid >> 5;
    ulonglong2* myX = sX + warp*256;
    ull cinit0 = pk2(g_c[lane], 0.f);
    ull cinit1 = pk2(g_c[32 + lane], 0.f);
    int nb = (blockIdx.x*8 + warp)*8;
    const ull* hin64 = (const ull*)hin;
    const ull* min64 = (const ull*)min;

    #pragma unroll
    for (int t = 0; t < 8; ++t) {
        ull mv = min64[(nb + t)*32 + lane];
        ull hv = hin64[(nb + t)*32 + lane];
        myX[t*32 + lane] = make_ulonglong2(mv, hv);
    }
    __syncwarp();

    ull acc0[8], acc1[8];
    #pragma unroll
    for (int t = 0; t < 8; ++t) { acc0[t] = cinit0; acc1[t] = cinit1; }
    const ulonglong2* wa = (const ulonglong2*)sWA;
    const ulonglong2* wb = (const ulonglong2*)sWB;
    #pragma unroll 4
    for (int kp = 0; kp < 32; ++kp) {
        ulonglong2 A = wa[kp*32 + lane];
        ulonglong2 B = wb[kp*32 + lane];
        #pragma unroll
        for (int t = 0; t < 8; ++t) {
            ulonglong2 xv = myX[t*32 + kp];  // broadcast
            acc0[t] = ff2(A.x, xv.x, acc0[t]);
            acc0[t] = ff2(B.x, xv.y, acc0[t]);
            acc1[t] = ff2(A.y, xv.x, acc1[t]);
            acc1[t] = ff2(B.y, xv.y, acc1[t]);
        }
    }
    float alo[8], ahi[8], s[8];
    #pragma unroll
    for (int t = 0; t < 8; ++t) {
        float2 p0 = up2(acc0[t]), p1 = up2(acc1[t]);
        alo[t] = fmaxf(p0.x + p0.y, 0.f);
        ahi[t] = fmaxf(p1.x + p1.y, 0.f);
        s[t] = alo[t]*alo[t] + ahi[t]*ahi[t];
    }
    #pragma unroll
    for (int off = 16; off; off >>= 1) {
        #pragma unroll
        for (int t = 0; t < 8; ++t) s[t] += __shfl_xor_sync(0xffffffffu, s[t], off);
    }
    #pragma unroll
    for (int t = 0; t < 8; ++t) {
        float rn = rsqrtf(s[t]);
        hout[(nb + t)*64 + lane]      = alo[t]*rn;
        hout[(nb + t)*64 + 32 + lane] = ahi[t]*rn;
    }
}

// ---- Ag, 256 blocks (o x graph-chunk), 4 graphs/warp/pass; also zero g_deg ----
__global__ void k_ag(const float* __restrict__ W5, const float* __restrict__ hfin) {
    __shared__ __align__(16) float sWT[4096];     // [j][i]
    __shared__ __align__(16) float2 sL[8][4][64];
    int bi = blockIdx.x, tid = threadIdx.x;
    int o = bi >> 2, gc = bi & 3;
    if (tid < 128) g_deg[bi*128 + tid] = 0;       // reset cursors for next replay
    for (int e = tid; e < 4096; e += 256) {
        int i = e >> 6, j = e & 63;
        sWT[j*64 + i] = W5[o*4096 + e];
    }
    __syncthreads();
    int lane = tid & 31, warp = tid >> 5;
    const ull* wp = (const ull*)sWT;
    for (int pass = 0; pass < 2; ++pass) {
        int gbase = gc*64 + pass*32 + warp*4;
        #pragma unroll
        for (int t = 0; t < 4; ++t) {
            int g = gbase + t;
            float2 v = ((const float2*)hfin)[(g*128 + 127)*32 + lane];
            sL[warp][t][2*lane]     = make_float2(v.x, v.x);
            sL[warp][t][2*lane + 1] = make_float2(v.y, v.y);
        }
        __syncwarp();
        ull acc[4] = {0ULL, 0ULL, 0ULL, 0ULL};
        #pragma unroll 2
        for (int j = 0; j < 64; ++j) {
            ull w = wp[j*32 + lane];
            #pragma unroll
            for (int t = 0; t < 4; ++t) {
                ull xv = *(const ull*)&sL[warp][t][j];
                acc[t] = ff2(w, xv, acc[t]);
            }
        }
        __syncwarp();
        #pragma unroll
        for (int t = 0; t < 4; ++t) {
            int g = gbase + t;
            ((float2*)(g_Ag + g*4096 + o*64))[lane] = up2(acc[t]);
        }
    }
}

// ---- fused y1 + head, 4 rows/warp/pass ----
__global__ void k_y1h(const float* __restrict__ hfin, const float* __restrict__ b5,
                      const float* __restrict__ Wd1, const float* __restrict__ bd1,
                      const float* __restrict__ Wd2, const float* __restrict__ bd2,
                      float* __restrict__ out) {
    extern __shared__ __align__(16) float dyn[];
    float*  sAgT = dyn;                   // 4096 [i][o]
    float*  sW1T = dyn + 4096;            // 8192 [k][j]
    float2* sY   = (float2*)(dyn + 4096 + 8192);  // 8*4*64 float2
    float*  sb5  = dyn + 4096 + 8192 + 4096;
    float*  sb1  = sb5 + 64;
    float*  sW2  = sb1 + 128;
    int g = blockIdx.x, tid = threadIdx.x;
    for (int e = tid; e < 4096; e += 256) {
        int o = e & 63, i = e >> 6;
        sAgT[i*64 + o] = g_Ag[g*4096 + o*64 + i];
    }
    for (int e = tid; e < 8192; e += 256) {
        int j = e >> 6, k = e & 63;
        sW1T[k*128 + j] = Wd1[e];
    }
    if (tid < 64) sb5[tid] = b5[tid];
    if (tid < 128) { sb1[tid] = bd1[tid]; sW2[tid] = Wd2[tid]; }
    __syncthreads();
    float bias2 = bd2[0];
    int lane = tid & 31, warp = tid >> 5;
    float2 (*sy)[64] = (float2 (*)[64])(sY + warp*256);
    const ull* ap = (const ull*)sAgT;
    const ulonglong2* wp = (const ulonglong2*)sW1T;
    const ull* b5p = (const ull*)sb5;
    for (int pass = 0; pass < 4; ++pass) {
        int rbase = pass*32 + warp*4;
        #pragma unroll
        for (int t = 0; t < 4; ++t) {
            int r = rbase + t;
            float2 v = (r < 127) ? ((const float2*)hfin)[(g*128 + r)*32 + lane]
                                 : make_float2(0.f, 0.f);
            sy[t][2*lane]     = make_float2(v.x, v.x);
            sy[t][2*lane + 1] = make_float2(v.y, v.y);
        }
        __syncwarp();
        ull ya[4];
        #pragma unroll
        for (int t = 0; t < 4; ++t) ya[t] = b5p[lane];
        #pragma unroll 2
        for (int i = 0; i < 64; ++i) {
            ull a = ap[i*32 + lane];
            #pragma unroll
            for (int t = 0; t < 4; ++t) {
                ull xv = *(const ull*)&sy[t][i];
                ya[t] = ff2(a, xv, ya[t]);
            }
        }
        __syncwarp();
        #pragma unroll
        for (int t = 0; t < 4; ++t) {
            float2 y = up2(ya[t]);
            sy[t][2*lane]     = make_float2(y.x, y.x);
            sy[t][2*lane + 1] = make_float2(y.y, y.y);
        }
        __syncwarp();
        ull z01[4], z23[4];
        #pragma unroll
        for (int t = 0; t < 4; ++t) {
            z01[t] = pk2(sb1[4*lane], sb1[4*lane + 1]);
            z23[t] = pk2(sb1[4*lane + 2], sb1[4*lane + 3]);
        }
        #pragma unroll 2
        for (int k = 0; k < 64; ++k) {
            ulonglong2 wv = wp[k*32 + lane];
            #pragma unroll
            for (int t = 0; t < 4; ++t) {
                ull yy = *(const ull*)&sy[t][k];
                z01[t] = ff2(wv.x, yy, z01[t]);
                z23[t] = ff2(wv.y, yy, z23[t]);
            }
        }
        __syncwarp();
        float4 w2 = *(float4*)&sW2[4*lane];
        #pragma unroll
        for (int t = 0; t < 4; ++t) {
            float2 za = up2(z01[t]), zb = up2(z23[t]);
            float acc = fmaxf(za.x, 0.f)*w2.x + fmaxf(za.y, 0.f)*w2.y +
                        fmaxf(zb.x, 0.f)*w2.z + fmaxf(zb.y, 0.f)*w2.w;
            #pragma unroll
            for (int off = 16; off; off >>= 1)
                acc += __shfl_xor_sync(0xffffffffu, acc, off);
            int r = rbase + t;
            if (lane == 0 && r < 127) out[g*127 + r] = acc + bias2;
        }
    }
}

extern "C" void kernel_launch(void* const* d_in, const int* in_sizes, int n_in,
                              void* d_out, int out_size) {
    const float* x = (const float*)d_in[0];
    const void*  ei = d_in[1];
    int base = (in_sizes[3] == 1) ? 4 : 3;
    const float* W1  = (const float*)d_in[base + 0];
    const float* b1  = (const float*)d_in[base + 1];
    const float* W2  = (const float*)d_in[base + 2];
    const float* b2  = (const float*)d_in[base + 3];
    const float* W3  = (const float*)d_in[base + 4];
    const float* b3  = (const float*)d_in[base + 5];
    const float* W4  = (const float*)d_in[base + 6];
    const float* b4  = (const float*)d_in[base + 7];
    const float* W5  = (const float*)d_in[base + 8];
    const float* b5  = (const float*)d_in[base + 9];
    const float* Wd1 = (const float*)d_in[base + 10];
    const float* bd1 = (const float*)d_in[base + 11];
    const float* Wd2 = (const float*)d_in[base + 12];
    const float* bd2 = (const float*)d_in[base + 13];
    float* out = (float*)d_out;

    float *hA = nullptr, *hB = nullptr, *ms = nullptr;
    cudaGetSymbolAddress((void**)&hA, g_h);
    cudaGetSymbolAddress((void**)&hB, g_m);
    cudaGetSymbolAddress((void**)&ms, g_s);

    cudaFuncSetAttribute(k_up,  cudaFuncAttributeMaxDynamicSharedMemorySize, 72*1024);
    cudaFuncSetAttribute(k_y1h, cudaFuncAttributeMaxDynamicSharedMemorySize, 72*1024);
    int up_smem  = 4096 * 16;                                 // 64KB
    int y1h_smem = (4096 + 8192 + 4096 + 64 + 128 + 128) * 4; // ~66KB

    k_pi<<<1553, 256>>>(x, ei, W1, b1, W2, b2, W3, b3, W4, b4);   // 1: input + CSR fill
    k_gat<<<NN/64, 512>>>(hA, ms);                                 // 2: gather d0
    k_up<<<NN/64, 256, up_smem>>>(hA, ms, hB);                     // 3: update d0
    k_gat<<<NN/64, 512>>>(hB, ms);                                 // 4: gather d1 <- ncu capture
    k_up<<<NN/64, 256, up_smem>>>(hB, ms, hA);                     // 5: update d1
    k_gat<<<NN/64, 512>>>(hA, ms);                                 // 6: gather d2
    k_up<<<NN/64, 256, up_smem>>>(hA, ms, hB);                     // 7: update d2
    k_ag<<<256, 256>>>(W5, hB);                                    // 8
    k_y1h<<<GG, 256, y1h_smem>>>(hB, b5, Wd1, bd1, Wd2, bd2, out); // 9
}

// round 15
// speedup vs baseline: 1.0602x; 1.0602x over previous
#include <cuda_runtime.h>

#define NN 32768
#define GG 256
#define PP 128
#define EE 524288
#define HH 64
#define CAP 96
#define ROWS (GG*(PP-1))

typedef unsigned long long ull;

// ---- device scratch ----
__device__ __align__(16) float g_h[(NN+1)*HH];   // +1 sentinel zero row
__device__ __align__(16) float g_m[(NN+1)*HH];
__device__ __align__(16) float g_s[NN*HH];       // gathered messages scratch
__device__ __align__(16) float g_Ag[GG*HH*HH];
__device__ __align__(16) float g_AB[HH*HH*2];    // A table [0,4096), B table [4096,8192), k-pair packed
__device__ __align__(16) float g_c[HH];
__device__ __align__(16) int g_deg[NN];          // zeroed at end of k_ag each replay
__device__ int g_srcl[NN*CAP];

// ---- f32x2 helpers ----
__device__ __forceinline__ ull pk2(float x, float y) {
    ull r; asm("mov.b64 %0,{%1,%2};" : "=l"(r) : "f"(x), "f"(y)); return r;
}
__device__ __forceinline__ ull ff2(ull a, ull b, ull c) {
    ull d; asm("fma.rn.f32x2 %0,%1,%2,%3;" : "=l"(d) : "l"(a), "l"(b), "l"(c)); return d;
}
__device__ __forceinline__ ull ad2(ull a, ull b) {
    ull d; asm("add.rn.f32x2 %0,%1,%2;" : "=l"(d) : "l"(a), "l"(b)); return d;
}
__device__ __forceinline__ float2 up2(ull a) {
    float x, y; asm("mov.b64 {%0,%1},%2;" : "=f"(x), "=f"(y) : "l"(a));
    return make_float2(x, y);
}

// ---- launch 1: weights (blk 0-15), bias+sentinel (blk 16), input layer (17-528),
//                CSR bucket fill (blk 529-1552, overlapped) ----
__global__ void k_pi(const float* __restrict__ x, const void* __restrict__ ei,
                     const float* __restrict__ W1, const float* __restrict__ b1,
                     const float* __restrict__ W2, const float* __restrict__ b2,
                     const float* __restrict__ W3, const float* __restrict__ b3,
                     const float* __restrict__ W4, const float* __restrict__ b4) {
    int tid = threadIdx.x;
    if (blockIdx.x >= 529) {
        // ---- CSR fill, 2 edges/thread; local int64 detection (256 high-words) ----
        const int* ei32 = (const int*)ei;
        int bad = (ei32[2*tid + 1] != 0);
        int is64 = !__syncthreads_or(bad);
        int e = ((int)(blockIdx.x - 529)*256 + tid)*2;
        int s0, s1, d0, d1;
        if (is64) {
            longlong2 sv = *(const longlong2*)((const long long*)ei + e);
            longlong2 dv = *(const longlong2*)((const long long*)ei + EE + e);
            s0 = (int)sv.x; s1 = (int)sv.y; d0 = (int)dv.x; d1 = (int)dv.y;
        } else {
            int2 sv = *(const int2*)(ei32 + e);
            int2 dv = *(const int2*)(ei32 + EE + e);
            s0 = sv.x; s1 = sv.y; d0 = dv.x; d1 = dv.y;
        }
        int p0 = atomicAdd(&g_deg[d0], 1);
        g_srcl[d0*CAP + p0] = s0;
        int p1 = atomicAdd(&g_deg[d1], 1);
        g_srcl[d1*CAP + p1] = s1;
        return;
    }
    if (blockIdx.x < 16) {
        int e = blockIdx.x * 256 + tid;
        int o = e >> 6, k = e & 63;
        float a = 0.f, b = 0.f;
        for (int t = 0; t < 64; ++t) {
            a += W4[o*128 + t]      * W3[t*64 + k];
            b += W4[o*128 + 64 + t] * W2[t*64 + k];
        }
        // k-pair packed: float4 at (kp*32 + (o&31)) = {X[o][2kp],X[o][2kp+1],X[o+32][2kp],X[o+32][2kp+1]}
        int kp = k >> 1, ob = o & 31, comp = ((o >> 5) << 1) | (k & 1);
        g_AB[(kp*32 + ob)*4 + comp]        = a;
        g_AB[4096 + (kp*32 + ob)*4 + comp] = b;
        return;
    }
    if (blockIdx.x == 16) {
        if (tid < 64) {
            float c = b4[tid];
            for (int t = 0; t < 64; ++t)
                c += W4[tid*128 + t]*b3[t] + W4[tid*128 + 64 + t]*b2[t];
            g_c[tid] = c;
            g_h[NN*64 + tid] = 0.f;   // sentinel rows
            g_m[NN*64 + tid] = 0.f;
        }
        return;
    }
    // ---- input layer ----
    __shared__ __align__(16) float sW[8*64];
    __shared__ float sb[64];
    for (int e = tid; e < 512; e += 256) {
        int o = e >> 3, j = e & 7;
        sW[j*64 + o] = W1[e];
    }
    if (tid < 64) sb[tid] = b1[tid];
    __syncthreads();
    int lane = tid & 31, warp = tid >> 5;
    for (int node = (blockIdx.x - 17)*8 + warp; node < NN; node += 512*8) {
        float xv = (lane < 8) ? x[node*8 + lane] : 0.f;
        float a0 = sb[2*lane], a1 = sb[2*lane + 1];
        #pragma unroll
        for (int j = 0; j < 8; ++j) {
            float xj = __shfl_sync(0xffffffffu, xv, j);
            a0 += sW[j*64 + 2*lane]     * xj;
            a1 += sW[j*64 + 2*lane + 1] * xj;
        }
        a0 = fmaxf(a0, 0.f); a1 = fmaxf(a1, 0.f);
        float s = a0*a0 + a1*a1;
        #pragma unroll
        for (int off = 16; off; off >>= 1) s += __shfl_xor_sync(0xffffffffu, s, off);
        float rn = rsqrtf(s);
        ((float2*)g_h)[node*32 + lane] = make_float2(a0*rn, a1*rn);
    }
}

// ---- pure gather (R13 measured optimum): ull loads, 4 nodes/warp ----
__global__ void __launch_bounds__(512)
k_gat(const float* __restrict__ hin, float* __restrict__ mout) {
    int tid = threadIdx.x;
    int lane = tid & 31, warp = tid >> 5;
    int nb = (blockIdx.x*16 + warp)*4;
    const ull* hin64 = (const ull*)hin;
    ull* mout64 = (ull*)mout;
    int deg[4], idx[4];
    #pragma unroll
    for (int t = 0; t < 4; ++t) deg[t] = g_deg[nb + t];
    #pragma unroll
    for (int t = 0; t < 4; ++t) {
        int n = deg[t] < 32 ? deg[t] : 32;
        idx[t] = (lane < n) ? g_srcl[(nb + t)*CAP + lane] : NN;
    }
    #pragma unroll
    for (int t = 0; t < 4; ++t) {
        int n = deg[t] < 32 ? deg[t] : 32;
        ull m0 = 0ULL, m1 = 0ULL;
        int nr = (n + 7) & ~7;
        #pragma unroll 8
        for (int j = 0; j < nr; j += 2) {
            int sa = __shfl_sync(0xffffffffu, idx[t], j);
            int sb = __shfl_sync(0xffffffffu, idx[t], j + 1);
            m0 = ad2(m0, hin64[sa*32 + lane]);
            m1 = ad2(m1, hin64[sb*32 + lane]);
        }
        for (int b = 32; b < deg[t]; b += 32) {   // rare tail (deg > 32)
            int nn = deg[t] - b; if (nn > 32) nn = 32;
            int id2 = (lane < nn) ? g_srcl[(nb + t)*CAP + b + lane] : NN;
            for (int j = 0; j < nn; ++j) {
                int s = __shfl_sync(0xffffffffu, id2, j);
                m0 = ad2(m0, hin64[s*32 + lane]);
            }
        }
        mout64[(nb + t)*32 + lane] = ad2(m0, m1);
    }
}

// ---- dense update: 10 nodes/warp, grid 410 <= 444 slots -> single block wave ----
__global__ void __launch_bounds__(256, 3)
k_up(const float* __restrict__ hin, const float* __restrict__ min,
     float* __restrict__ hout) {
    extern __shared__ __align__(16) float4 dynsm[];
    float4* sWA = dynsm;          // 1024 float4 = 16KB
    float4* sWB = dynsm + 1024;   // 1024 float4 = 16KB
    ulonglong2* sX = (ulonglong2*)(dynsm + 2048);  // 8 warps * 10 nodes * 32 kp = 40KB
    int tid = threadIdx.x;
    for (int e = tid; e < 2048; e += 256) sWA[e] = ((const float4*)g_AB)[e];
    __syncthreads();
    int lane = tid & 31, warp = tid >> 5;
    ulonglong2* myX = sX + warp*320;
    ull cinit0 = pk2(g_c[lane], 0.f);
    ull cinit1 = pk2(g_c[32 + lane], 0.f);
    int nb = (blockIdx.x*8 + warp)*10;
    const ull* hin64 = (const ull*)hin;
    const ull* min64 = (const ull*)min;

    #pragma unroll
    for (int t = 0; t < 10; ++t) {
        int node = nb + t;
        int na = node < NN ? node : NN;   // sentinel-safe (g_h/g_m have row NN); min uses row 0 guard below
        ull mv = (node < NN) ? min64[node*32 + lane] : 0ULL;
        ull hv = hin64[na*32 + lane];
        myX[t*32 + lane] = make_ulonglong2(mv, hv);
    }
    __syncwarp();

    ull acc0[10], acc1[10];
    #pragma unroll
    for (int t = 0; t < 10; ++t) { acc0[t] = cinit0; acc1[t] = cinit1; }
    const ulonglong2* wa = (const ulonglong2*)sWA;
    const ulonglong2* wb = (const ulonglong2*)sWB;
    #pragma unroll 4
    for (int kp = 0; kp < 32; ++kp) {
        ulonglong2 A = wa[kp*32 + lane];
        ulonglong2 B = wb[kp*32 + lane];
        #pragma unroll
        for (int t = 0; t < 10; ++t) {
            ulonglong2 xv = myX[t*32 + kp];  // broadcast
            acc0[t] = ff2(A.x, xv.x, acc0[t]);
            acc0[t] = ff2(B.x, xv.y, acc0[t]);
            acc1[t] = ff2(A.y, xv.x, acc1[t]);
            acc1[t] = ff2(B.y, xv.y, acc1[t]);
        }
    }
    float alo[10], ahi[10], s[10];
    #pragma unroll
    for (int t = 0; t < 10; ++t) {
        float2 p0 = up2(acc0[t]), p1 = up2(acc1[t]);
        alo[t] = fmaxf(p0.x + p0.y, 0.f);
        ahi[t] = fmaxf(p1.x + p1.y, 0.f);
        s[t] = alo[t]*alo[t] + ahi[t]*ahi[t];
    }
    #pragma unroll
    for (int off = 16; off; off >>= 1) {
        #pragma unroll
        for (int t = 0; t < 10; ++t) s[t] += __shfl_xor_sync(0xffffffffu, s[t], off);
    }
    #pragma unroll
    for (int t = 0; t < 10; ++t) {
        int node = nb + t;
        if (node < NN) {
            float rn = rsqrtf(s[t]);
            hout[node*64 + lane]      = alo[t]*rn;
            hout[node*64 + 32 + lane] = ahi[t]*rn;
        }
    }
}

// ---- Ag, 256 blocks (o x graph-chunk), 4 graphs/warp/pass; also zero g_deg ----
__global__ void k_ag(const float* __restrict__ W5, const float* __restrict__ hfin) {
    __shared__ __align__(16) float sWT[4096];     // [j][i]
    __shared__ __align__(16) float2 sL[8][4][64];
    int bi = blockIdx.x, tid = threadIdx.x;
    int o = bi >> 2, gc = bi & 3;
    if (tid < 128) g_deg[bi*128 + tid] = 0;       // reset cursors for next replay
    for (int e = tid; e < 4096; e += 256) {
        int i = e >> 6, j = e & 63;
        sWT[j*64 + i] = W5[o*4096 + e];
    }
    __syncthreads();
    int lane = tid & 31, warp = tid >> 5;
    const ull* wp = (const ull*)sWT;
    for (int pass = 0; pass < 2; ++pass) {
        int gbase = gc*64 + pass*32 + warp*4;
        #pragma unroll
        for (int t = 0; t < 4; ++t) {
            int g = gbase + t;
            float2 v = ((const float2*)hfin)[(g*128 + 127)*32 + lane];
            sL[warp][t][2*lane]     = make_float2(v.x, v.x);
            sL[warp][t][2*lane + 1] = make_float2(v.y, v.y);
        }
        __syncwarp();
        ull acc[4] = {0ULL, 0ULL, 0ULL, 0ULL};
        #pragma unroll 2
        for (int j = 0; j < 64; ++j) {
            ull w = wp[j*32 + lane];
            #pragma unroll
            for (int t = 0; t < 4; ++t) {
                ull xv = *(const ull*)&sL[warp][t][j];
                acc[t] = ff2(w, xv, acc[t]);
            }
        }
        __syncwarp();
        #pragma unroll
        for (int t = 0; t < 4; ++t) {
            int g = gbase + t;
            ((float2*)(g_Ag + g*4096 + o*64))[lane] = up2(acc[t]);
        }
    }
}

// ---- fused y1 + head, 4 rows/warp/pass ----
__global__ void k_y1h(const float* __restrict__ hfin, const float* __restrict__ b5,
                      const float* __restrict__ Wd1, const float* __restrict__ bd1,
                      const float* __restrict__ Wd2, const float* __restrict__ bd2,
                      float* __restrict__ out) {
    extern __shared__ __align__(16) float dyn[];
    float*  sAgT = dyn;                   // 4096 [i][o]
    float*  sW1T = dyn + 4096;            // 8192 [k][j]
    float2* sY   = (float2*)(dyn + 4096 + 8192);  // 8*4*64 float2
    float*  sb5  = dyn + 4096 + 8192 + 4096;
    float*  sb1  = sb5 + 64;
    float*  sW2  = sb1 + 128;
    int g = blockIdx.x, tid = threadIdx.x;
    for (int e = tid; e < 4096; e += 256) {
        int o = e & 63, i = e >> 6;
        sAgT[i*64 + o] = g_Ag[g*4096 + o*64 + i];
    }
    for (int e = tid; e < 8192; e += 256) {
        int j = e >> 6, k = e & 63;
        sW1T[k*128 + j] = Wd1[e];
    }
    if (tid < 64) sb5[tid] = b5[tid];
    if (tid < 128) { sb1[tid] = bd1[tid]; sW2[tid] = Wd2[tid]; }
    __syncthreads();
    float bias2 = bd2[0];
    int lane = tid & 31, warp = tid >> 5;
    float2 (*sy)[64] = (float2 (*)[64])(sY + warp*256);
    const ull* ap = (const ull*)sAgT;
    const ulonglong2* wp = (const ulonglong2*)sW1T;
    const ull* b5p = (const ull*)sb5;
    for (int pass = 0; pass < 4; ++pass) {
        int rbase = pass*32 + warp*4;
        #pragma unroll
        for (int t = 0; t < 4; ++t) {
            int r = rbase + t;
            float2 v = (r < 127) ? ((const float2*)hfin)[(g*128 + r)*32 + lane]
                                 : make_float2(0.f, 0.f);
            sy[t][2*lane]     = make_float2(v.x, v.x);
            sy[t][2*lane + 1] = make_float2(v.y, v.y);
        }
        __syncwarp();
        ull ya[4];
        #pragma unroll
        for (int t = 0; t < 4; ++t) ya[t] = b5p[lane];
        #pragma unroll 2
        for (int i = 0; i < 64; ++i) {
            ull a = ap[i*32 + lane];
            #pragma unroll
            for (int t = 0; t < 4; ++t) {
                ull xv = *(const ull*)&sy[t][i];
                ya[t] = ff2(a, xv, ya[t]);
            }
        }
        __syncwarp();
        #pragma unroll
        for (int t = 0; t < 4; ++t) {
            float2 y = up2(ya[t]);
            sy[t][2*lane]     = make_float2(y.x, y.x);
            sy[t][2*lane + 1] = make_float2(y.y, y.y);
        }
        __syncwarp();
        ull z01[4], z23[4];
        #pragma unroll
        for (int t = 0; t < 4; ++t) {
            z01[t] = pk2(sb1[4*lane], sb1[4*lane + 1]);
            z23[t] = pk2(sb1[4*lane + 2], sb1[4*lane + 3]);
        }
        #pragma unroll 2
        for (int k = 0; k < 64; ++k) {
            ulonglong2 wv = wp[k*32 + lane];
            #pragma unroll
            for (int t = 0; t < 4; ++t) {
                ull yy = *(const ull*)&sy[t][k];
                z01[t] = ff2(wv.x, yy, z01[t]);
                z23[t] = ff2(wv.y, yy, z23[t]);
            }
        }
        __syncwarp();
        float4 w2 = *(float4*)&sW2[4*lane];
        #pragma unroll
        for (int t = 0; t < 4; ++t) {
            float2 za = up2(z01[t]), zb = up2(z23[t]);
            float acc = fmaxf(za.x, 0.f)*w2.x + fmaxf(za.y, 0.f)*w2.y +
                        fmaxf(zb.x, 0.f)*w2.z + fmaxf(zb.y, 0.f)*w2.w;
            #pragma unroll
            for (int off = 16; off; off >>= 1)
                acc += __shfl_xor_sync(0xffffffffu, acc, off);
            int r = rbase + t;
            if (lane == 0 && r < 127) out[g*127 + r] = acc + bias2;
        }
    }
}

extern "C" void kernel_launch(void* const* d_in, const int* in_sizes, int n_in,
                              void* d_out, int out_size) {
    const float* x = (const float*)d_in[0];
    const void*  ei = d_in[1];
    int base = (in_sizes[3] == 1) ? 4 : 3;
    const float* W1  = (const float*)d_in[base + 0];
    const float* b1  = (const float*)d_in[base + 1];
    const float* W2  = (const float*)d_in[base + 2];
    const float* b2  = (const float*)d_in[base + 3];
    const float* W3  = (const float*)d_in[base + 4];
    const float* b3  = (const float*)d_in[base + 5];
    const float* W4  = (const float*)d_in[base + 6];
    const float* b4  = (const float*)d_in[base + 7];
    const float* W5  = (const float*)d_in[base + 8];
    const float* b5  = (const float*)d_in[base + 9];
    const float* Wd1 = (const float*)d_in[base + 10];
    const float* bd1 = (const float*)d_in[base + 11];
    const float* Wd2 = (const float*)d_in[base + 12];
    const float* bd2 = (const float*)d_in[base + 13];
    float* out = (float*)d_out;

    float *hA = nullptr, *hB = nullptr, *ms = nullptr;
    cudaGetSymbolAddress((void**)&hA, g_h);
    cudaGetSymbolAddress((void**)&hB, g_m);
    cudaGetSymbolAddress((void**)&ms, g_s);

    cudaFuncSetAttribute(k_up,  cudaFuncAttributeMaxDynamicSharedMemorySize, 76*1024);
    cudaFuncSetAttribute(k_y1h, cudaFuncAttributeMaxDynamicSharedMemorySize, 72*1024);
    int up_smem  = (2048 + 2560) * 16;                        // 72KB (32KB weights + 40KB staging)
    int y1h_smem = (4096 + 8192 + 4096 + 64 + 128 + 128) * 4; // ~66KB

    int up_grid = (NN + 79) / 80;   // 410 blocks of 8 warps * 10 nodes

    k_pi<<<1553, 256>>>(x, ei, W1, b1, W2, b2, W3, b3, W4, b4);   // 1: input + CSR fill
    k_gat<<<NN/64, 512>>>(hA, ms);                                 // 2: gather d0
    k_up<<<up_grid, 256, up_smem>>>(hA, ms, hB);                   // 3: update d0
    k_gat<<<NN/64, 512>>>(hB, ms);                                 // 4: gather d1 <- ncu capture
    k_up<<<up_grid, 256, up_smem>>>(hB, ms, hA);                   // 5: update d1
    k_gat<<<NN/64, 512>>>(hA, ms);                                 // 6: gather d2
    k_up<<<up_grid, 256, up_smem>>>(hA, ms, hB);                   // 7: update d2
    k_ag<<<256, 256>>>(W5, hB);                                    // 8
    k_y1h<<<GG, 256, y1h_smem>>>(hB, b5, Wd1, bd1, Wd2, bd2, out); // 9
}